// round 4
// baseline (speedup 1.0000x reference)
#include <cuda_runtime.h>
#include <cstdint>
#include <math.h>

#define BB 32
#define TT 128
#define VV 16000
#define EE 512
#define ZZ 128
#define HH 1024
#define RR 64   // 2*B rows: [0,32)=free-running (stream 0), [32,64)=teacher (stream 1)
#define START_ID 1

// ---------------- device state (persists across replays -> re-init each launch) ----
__device__ float g_h0[RR][HH];
__device__ float g_c0[RR][HH];
__device__ float g_h1[RR][HH];
__device__ float g_c1[RR][HH];
__device__ float g_gates[RR][4*HH];
__device__ float g_logits[RR][VV];
__device__ int   g_tok[RR];

// ---------------- init ----------------
__global__ void init_kernel() {
    int i = blockIdx.x * blockDim.x + threadIdx.x;
    if (i < RR * HH) {
        ((float*)g_h0)[i] = 0.f;
        ((float*)g_c0)[i] = 0.f;
        ((float*)g_h1)[i] = 0.f;
        ((float*)g_c1)[i] = 0.f;
    }
    if (i < RR) g_tok[i] = START_ID;
}

// ---------------- threefry2x32 (exact JAX semantics) ----------------
__host__ __device__ __forceinline__ uint32_t rotl32(uint32_t v, int d) {
    return (v << d) | (v >> (32 - d));
}

__host__ __device__ __forceinline__ void threefry2x32(
    uint32_t k0, uint32_t k1, uint32_t x0, uint32_t x1,
    uint32_t* o0, uint32_t* o1)
{
    uint32_t ks2 = k0 ^ k1 ^ 0x1BD11BDAu;
    x0 += k0; x1 += k1;
#define TF_RND(R_) { x0 += x1; x1 = rotl32(x1, R_); x1 ^= x0; }
    TF_RND(13) TF_RND(15) TF_RND(26) TF_RND(6)
    x0 += k1;  x1 += ks2 + 1u;
    TF_RND(17) TF_RND(29) TF_RND(16) TF_RND(24)
    x0 += ks2; x1 += k0 + 2u;
    TF_RND(13) TF_RND(15) TF_RND(26) TF_RND(6)
    x0 += k0;  x1 += k1 + 3u;
    TF_RND(17) TF_RND(29) TF_RND(16) TF_RND(24)
    x0 += k1;  x1 += ks2 + 4u;
    TF_RND(13) TF_RND(15) TF_RND(26) TF_RND(6)
    x0 += ks2; x1 += k0 + 5u;
#undef TF_RND
    *o0 = x0; *o1 = x1;
}

// fold_in(key, data) = threefry2x32(key, [0, data])  (unaffected by partitionable flag)
static void h_fold(uint32_t k0, uint32_t k1, uint32_t data, uint32_t* o0, uint32_t* o1) {
    threefry2x32(k0, k1, 0u, data, o0, o1);
}

// gumbel for flat index idx of a (32,16000) uint32 draw keyed by (k0,k1)
// JAX >= 0.4.30 default: jax_threefry_partitionable=True
//   counter = uint64(idx) -> block(x0 = hi32 = 0, x1 = lo32 = idx), bits = o0 ^ o1
__device__ __forceinline__ float jax_gumbel(uint32_t k0, uint32_t k1, uint32_t idx) {
    uint32_t o0, o1;
    threefry2x32(k0, k1, 0u, idx, &o0, &o1);
    uint32_t bits = o0 ^ o1;
    float f = __uint_as_float((bits >> 9) | 0x3f800000u) - 1.0f;  // [0,1)
    float u = fmaxf(f, 1.17549435e-38f);                          // minval = tiny
    return -logf(-logf(u));
}

// ---------------- GEMM: M=64, BN=128, Kc=16, 256 threads, 8x4 per-thread tile ---
// MODE 0: gates layer0, K=1664, A = [emb[tok] | z | h0], B = [Wx0 ; Wh0], C=g_gates
// MODE 1: gates layer1, K=2048, A = [h0 | h1],           B = [Wx1 ; Wh1], C=g_gates
// MODE 2: logits,       K=1024, A = h1,                  B = Wout,        C=g_logits
template<int MODE>
__global__ __launch_bounds__(256) void gemm_kernel(
    const float* __restrict__ emb, const float* __restrict__ z,
    const float* __restrict__ W1,  const float* __restrict__ W2,
    const float* __restrict__ bias)
{
    constexpr int K  = (MODE == 0) ? 1664 : ((MODE == 1) ? 2048 : 1024);

    __shared__ float As[16][64];
    __shared__ float Bs[16][128];
    __shared__ int   toks[64];

    const int tid = threadIdx.x;
    const int n0  = blockIdx.x * 128;
    const int tx  = tid & 31;        // 32 col-groups of 4
    const int ty  = tid >> 5;        // 8 row-groups of 8

    if (MODE == 0 && tid < 64) toks[tid] = g_tok[tid];
    __syncthreads();

    float acc[8][4];
#pragma unroll
    for (int i = 0; i < 8; i++)
#pragma unroll
        for (int j = 0; j < 4; j++) acc[i][j] = 0.f;

    const int rA = tid >> 2;          // A load: this thread's row (64 rows x 16 k)
    const int kkA = (tid & 3) * 4;    // 4 consecutive kk

    for (int k0 = 0; k0 < K; k0 += 16) {
        // ---- load A tile (gathered) ----
#pragma unroll
        for (int e = 0; e < 4; e++) {
            int kk = kkA + e;
            int k  = k0 + kk;
            float v;
            if (MODE == 0) {
                if (k < 512)       v = emb[(size_t)toks[rA] * EE + k];
                else if (k < 640)  v = z[(size_t)(rA & 31) * ZZ + (k - 512)];
                else               v = g_h0[rA][k - 640];
            } else if (MODE == 1) {
                v = (k < 1024) ? g_h0[rA][k] : g_h1[rA][k - 1024];
            } else {
                v = g_h1[rA][k];
            }
            As[kk][rA] = v;
        }
        // ---- load B tile (16 x 128) via float4 ----
        {
            int kk = tid >> 4;              // 16 rows, 16 threads per row
            int nn = (tid & 15) * 8;        // 8 consecutive cols
            int k  = k0 + kk;
            const float* row;
            if (MODE == 0)      row = (k < 640)  ? (W1 + (size_t)k * 4096)
                                                 : (W2 + (size_t)(k - 640) * 4096);
            else if (MODE == 1) row = (k < 1024) ? (W1 + (size_t)k * 4096)
                                                 : (W2 + (size_t)(k - 1024) * 4096);
            else                row = W1 + (size_t)k * VV;
            float4 v0 = *reinterpret_cast<const float4*>(row + n0 + nn);
            float4 v1 = *reinterpret_cast<const float4*>(row + n0 + nn + 4);
            *reinterpret_cast<float4*>(&Bs[kk][nn])     = v0;
            *reinterpret_cast<float4*>(&Bs[kk][nn + 4]) = v1;
        }
        __syncthreads();
        // ---- compute ----
#pragma unroll
        for (int kk = 0; kk < 16; kk++) {
            float4 b4 = *reinterpret_cast<const float4*>(&Bs[kk][tx * 4]);
            float a[8];
#pragma unroll
            for (int i = 0; i < 8; i++) a[i] = As[kk][ty * 8 + i];
#pragma unroll
            for (int i = 0; i < 8; i++) {
                acc[i][0] += a[i] * b4.x;
                acc[i][1] += a[i] * b4.y;
                acc[i][2] += a[i] * b4.z;
                acc[i][3] += a[i] * b4.w;
            }
        }
        __syncthreads();
    }

    // ---- epilogue: += bias, store ----
    const int ldc = (MODE == 2) ? VV : 4096;
    float* C = (MODE == 2) ? &g_logits[0][0] : &g_gates[0][0];
    const int nc = n0 + tx * 4;
    float4 bv = *reinterpret_cast<const float4*>(bias + nc);
#pragma unroll
    for (int i = 0; i < 8; i++) {
        int r = ty * 8 + i;
        float4 o;
        o.x = acc[i][0] + bv.x;
        o.y = acc[i][1] + bv.y;
        o.z = acc[i][2] + bv.z;
        o.w = acc[i][3] + bv.w;
        *reinterpret_cast<float4*>(C + (size_t)r * ldc + nc) = o;
    }
}

// ---------------- LSTM cell (gate order i,f,g,o) ----------------
__device__ __forceinline__ float sigf(float x) { return 1.f / (1.f + expf(-x)); }

__global__ void cell_kernel(int layer) {
    int idx = blockIdx.x * blockDim.x + threadIdx.x;
    if (idx >= RR * HH) return;
    int r = idx >> 10, j = idx & (HH - 1);
    float* hA = layer ? &g_h1[0][0] : &g_h0[0][0];
    float* cA = layer ? &g_c1[0][0] : &g_c0[0][0];
    float gi = g_gates[r][j];
    float gf = g_gates[r][j + HH];
    float gg = g_gates[r][j + 2 * HH];
    float go = g_gates[r][j + 3 * HH];
    float c  = cA[idx];
    c = sigf(gf) * c + sigf(gi) * tanhf(gg);
    float h = sigf(go) * tanhf(c);
    cA[idx] = c;
    hA[idx] = h;
}

// ---------------- softmax + p output + gumbel argmax sampling ----------------
__global__ __launch_bounds__(256) void sample_kernel(
    int t,
    uint32_t k0s0, uint32_t k1s0, uint32_t k0s1, uint32_t k1s1,
    const int* __restrict__ x, float* __restrict__ out)
{
    const int r   = blockIdx.x;
    const int tid = threadIdx.x;
    const int stream = (r < BB) ? 0 : 1;
    const int b   = r & 31;
    const float* L = g_logits[r];

    __shared__ float red[256];
    __shared__ int   redi[256];

    // pass 1: max
    float m = -INFINITY;
    for (int v = tid; v < VV; v += 256) m = fmaxf(m, L[v]);
    red[tid] = m; __syncthreads();
    for (int s = 128; s > 0; s >>= 1) {
        if (tid < s) red[tid] = fmaxf(red[tid], red[tid + s]);
        __syncthreads();
    }
    m = red[0]; __syncthreads();

    // pass 2: log-sum-exp
    float sum = 0.f;
    for (int v = tid; v < VV; v += 256) sum += expf(L[v] - m);
    red[tid] = sum; __syncthreads();
    for (int s = 128; s > 0; s >>= 1) {
        if (tid < s) red[tid] += red[tid + s];
        __syncthreads();
    }
    float lse = logf(red[0]); __syncthreads();

    // pass 3: write p, gumbel score, local argmax (first-index on ties)
    const uint32_t k0 = stream ? k0s1 : k0s0;
    const uint32_t k1 = stream ? k1s1 : k1s0;
    const size_t p_off = stream ? ((size_t)4096 + (size_t)BB * TT * VV + 4096)
                                : (size_t)4096;
    const size_t pbase = p_off + ((size_t)b * TT + t) * VV;

    float best = -INFINITY; int bidx = VV;
    for (int v = tid; v < VV; v += 256) {
        float lp = (L[v] - m) - lse;
        out[pbase + v] = expf(lp);
        float g = jax_gumbel(k0, k1, (uint32_t)(b * VV + v));
        float sc = lp + g;
        if (sc > best) { best = sc; bidx = v; }  // strictly > keeps first index
    }
    red[tid] = best; redi[tid] = bidx; __syncthreads();
    for (int s = 128; s > 0; s >>= 1) {
        if (tid < s) {
            float o = red[tid + s]; int oi = redi[tid + s];
            if (o > red[tid] || (o == red[tid] && oi < redi[tid])) {
                red[tid] = o; redi[tid] = oi;
            }
        }
        __syncthreads();
    }

    if (tid == 0) {
        int am = redi[0];
        size_t sbase = stream ? ((size_t)4096 + (size_t)BB * TT * VV) : (size_t)0;
        out[sbase + (size_t)b * TT + t] = (float)am;
        // next-step input token: free rows feed back sample; teacher rows use x[:, t]
        g_tok[r] = stream ? x[(size_t)b * TT + t] : am;
    }
}

// ---------------- host driver ----------------
extern "C" void kernel_launch(void* const* d_in, const int* in_sizes, int n_in,
                              void* d_out, int out_size)
{
    const int*   x    = (const int*)  d_in[0];
    const float* z    = (const float*)d_in[1];
    const float* emb  = (const float*)d_in[2];
    const float* Wx0  = (const float*)d_in[3];
    const float* Wh0  = (const float*)d_in[4];
    const float* b0   = (const float*)d_in[5];
    const float* Wx1  = (const float*)d_in[6];
    const float* Wh1  = (const float*)d_in[7];
    const float* b1   = (const float*)d_in[8];
    const float* Wout = (const float*)d_in[9];
    const float* bout = (const float*)d_in[10];
    float* out = (float*)d_out;

    init_kernel<<<256, 256>>>();

    // SAMPLE_KEY = jax.random.key(42) -> (0, 42); fold stream then t
    uint32_t s0a, s0b, s1a, s1b;
    h_fold(0u, 42u, 0u, &s0a, &s0b);
    h_fold(0u, 42u, 1u, &s1a, &s1b);

    for (int t = 0; t < TT; t++) {
        uint32_t k0s0, k1s0, k0s1, k1s1;
        h_fold(s0a, s0b, (uint32_t)t, &k0s0, &k1s0);
        h_fold(s1a, s1b, (uint32_t)t, &k0s1, &k1s1);

        gemm_kernel<0><<<32, 256>>>(emb, z, Wx0, Wh0, b0);
        cell_kernel<<<(RR * HH + 255) / 256, 256>>>(0);
        gemm_kernel<1><<<32, 256>>>(emb, z, Wx1, Wh1, b1);
        cell_kernel<<<(RR * HH + 255) / 256, 256>>>(1);
        gemm_kernel<2><<<VV / 128, 256>>>(emb, z, Wout, Wout, bout);
        sample_kernel<<<RR, 256>>>(t, k0s0, k1s0, k0s1, k1s1, x, out);
    }
}

// round 5
// speedup vs baseline: 2.7812x; 2.7812x over previous
#include <cuda_runtime.h>
#include <cstdint>
#include <math.h>

#define BB 32
#define TT 128
#define VV 16000
#define EE 512
#define ZZ 128
#define HH 1024
#define RR 64   // 2*B rows: [0,32)=free-running (stream 0), [32,64)=teacher (stream 1)
#define START_ID 1

// ---------------- device state ----------------
__device__ float g_h0[RR][HH];
__device__ float g_c0[RR][HH];
__device__ float g_h1[RR][HH];
__device__ float g_c1[RR][HH];
__device__ float g_part[4][RR][4*HH];   // split-K partials for gate GEMMs
__device__ float g_logits[RR][VV];
__device__ int   g_tok[RR];

// ---------------- init ----------------
__global__ void init_kernel() {
    int i = blockIdx.x * blockDim.x + threadIdx.x;
    if (i < RR * HH) {
        ((float*)g_h0)[i] = 0.f;
        ((float*)g_c0)[i] = 0.f;
        ((float*)g_h1)[i] = 0.f;
        ((float*)g_c1)[i] = 0.f;
    }
    if (i < RR) g_tok[i] = START_ID;
}

// ---------------- threefry2x32 (exact JAX semantics) ----------------
__host__ __device__ __forceinline__ uint32_t rotl32(uint32_t v, int d) {
    return (v << d) | (v >> (32 - d));
}

__host__ __device__ __forceinline__ void threefry2x32(
    uint32_t k0, uint32_t k1, uint32_t x0, uint32_t x1,
    uint32_t* o0, uint32_t* o1)
{
    uint32_t ks2 = k0 ^ k1 ^ 0x1BD11BDAu;
    x0 += k0; x1 += k1;
#define TF_RND(R_) { x0 += x1; x1 = rotl32(x1, R_); x1 ^= x0; }
    TF_RND(13) TF_RND(15) TF_RND(26) TF_RND(6)
    x0 += k1;  x1 += ks2 + 1u;
    TF_RND(17) TF_RND(29) TF_RND(16) TF_RND(24)
    x0 += ks2; x1 += k0 + 2u;
    TF_RND(13) TF_RND(15) TF_RND(26) TF_RND(6)
    x0 += k0;  x1 += k1 + 3u;
    TF_RND(17) TF_RND(29) TF_RND(16) TF_RND(24)
    x0 += k1;  x1 += ks2 + 4u;
    TF_RND(13) TF_RND(15) TF_RND(26) TF_RND(6)
    x0 += ks2; x1 += k0 + 5u;
#undef TF_RND
    *o0 = x0; *o1 = x1;
}

static void h_fold(uint32_t k0, uint32_t k1, uint32_t data, uint32_t* o0, uint32_t* o1) {
    threefry2x32(k0, k1, 0u, data, o0, o1);
}

// JAX >= 0.4.30 partitionable threefry: counter = u64(idx) -> (0, idx), bits = o0^o1
__device__ __forceinline__ float jax_gumbel(uint32_t k0, uint32_t k1, uint32_t idx) {
    uint32_t o0, o1;
    threefry2x32(k0, k1, 0u, idx, &o0, &o1);
    uint32_t bits = o0 ^ o1;
    float f = __uint_as_float((bits >> 9) | 0x3f800000u) - 1.0f;  // [0,1)
    float u = fmaxf(f, 1.17549435e-38f);                          // minval = tiny
    return -logf(-logf(u));
}

// ---------------- GEMM: M=64, BN=128, Kc=16, 256 thr, 8x4/thread, dbuf smem ----
// MODE 0: gates layer0, K=1664 (4 K-slices of 416), A=[emb[tok]|z|h0], B=[Wx0;Wh0]
// MODE 1: gates layer1, K=2048 (4 K-slices of 512), A=[h0|h1],         B=[Wx1;Wh1]
// MODE 2: logits,       K=1024 (1 slice),           A=h1,              B=Wout (+bias)
template<int MODE>
__device__ __forceinline__ void load_tile(
    int k0, int rA, int kkA, int n0, int tid,
    const float* __restrict__ emb, const float* __restrict__ z,
    const float* __restrict__ W1,  const float* __restrict__ W2,
    const int* toks, float pa[4], float4& pb0, float4& pb1)
{
#pragma unroll
    for (int e = 0; e < 4; e++) {
        int k = k0 + kkA + e;
        float v;
        if (MODE == 0) {
            if (k < 512)      v = emb[(size_t)toks[rA] * EE + k];
            else if (k < 640) v = z[(size_t)(rA & 31) * ZZ + (k - 512)];
            else              v = g_h0[rA][k - 640];
        } else if (MODE == 1) {
            v = (k < 1024) ? g_h0[rA][k] : g_h1[rA][k - 1024];
        } else {
            v = g_h1[rA][k];
        }
        pa[e] = v;
    }
    {
        int kk = tid >> 4;
        int nn = (tid & 15) * 8;
        int k  = k0 + kk;
        const float* row;
        if (MODE == 0)      row = (k < 640)  ? (W1 + (size_t)k * 4096)
                                             : (W2 + (size_t)(k - 640) * 4096);
        else if (MODE == 1) row = (k < 1024) ? (W1 + (size_t)k * 4096)
                                             : (W2 + (size_t)(k - 1024) * 4096);
        else                row = W1 + (size_t)k * VV;
        pb0 = *reinterpret_cast<const float4*>(row + n0 + nn);
        pb1 = *reinterpret_cast<const float4*>(row + n0 + nn + 4);
    }
}

template<int MODE>
__global__ __launch_bounds__(256) void gemm_kernel(
    const float* __restrict__ emb, const float* __restrict__ z,
    const float* __restrict__ W1,  const float* __restrict__ W2,
    const float* __restrict__ bias)
{
    constexpr int KTOT = (MODE == 0) ? 1664 : ((MODE == 1) ? 2048 : 1024);
    constexpr int KSL  = (MODE == 2) ? 1 : 4;
    constexpr int KS   = KTOT / KSL;     // 416 / 512 / 1024

    __shared__ float As[2][16][64];
    __shared__ float Bs[2][16][128];
    __shared__ int   toks[64];

    const int tid = threadIdx.x;
    const int n0  = blockIdx.x * 128;
    const int ks0 = blockIdx.y * KS;
    const int tx  = tid & 31;
    const int ty  = tid >> 5;
    const int rA  = tid >> 2;
    const int kkA = (tid & 3) * 4;

    if (MODE == 0) {
        if (tid < 64) toks[tid] = g_tok[tid];
        __syncthreads();
    }

    float acc[8][4];
#pragma unroll
    for (int i = 0; i < 8; i++)
#pragma unroll
        for (int j = 0; j < 4; j++) acc[i][j] = 0.f;

    float pa[4]; float4 pb0, pb1;

    // preload slice 0 -> buffer 0
    load_tile<MODE>(ks0, rA, kkA, n0, tid, emb, z, W1, W2, toks, pa, pb0, pb1);
    {
        int kk = tid >> 4, nn = (tid & 15) * 8;
#pragma unroll
        for (int e = 0; e < 4; e++) As[0][kkA + e][rA] = pa[e];
        *reinterpret_cast<float4*>(&Bs[0][kk][nn])     = pb0;
        *reinterpret_cast<float4*>(&Bs[0][kk][nn + 4]) = pb1;
    }
    __syncthreads();

    int buf = 0;
    for (int k0 = ks0; k0 < ks0 + KS; k0 += 16) {
        const bool more = (k0 + 16) < (ks0 + KS);
        if (more)
            load_tile<MODE>(k0 + 16, rA, kkA, n0, tid, emb, z, W1, W2, toks, pa, pb0, pb1);

        // compute current buffer
#pragma unroll
        for (int kk = 0; kk < 16; kk++) {
            float4 a0 = *reinterpret_cast<const float4*>(&As[buf][kk][ty * 8]);
            float4 a1 = *reinterpret_cast<const float4*>(&As[buf][kk][ty * 8 + 4]);
            float4 b4 = *reinterpret_cast<const float4*>(&Bs[buf][kk][tx * 4]);
            float a[8] = {a0.x, a0.y, a0.z, a0.w, a1.x, a1.y, a1.z, a1.w};
#pragma unroll
            for (int i = 0; i < 8; i++) {
                acc[i][0] += a[i] * b4.x;
                acc[i][1] += a[i] * b4.y;
                acc[i][2] += a[i] * b4.z;
                acc[i][3] += a[i] * b4.w;
            }
        }

        if (more) {
            int kk = tid >> 4, nn = (tid & 15) * 8;
            int nb = buf ^ 1;
#pragma unroll
            for (int e = 0; e < 4; e++) As[nb][kkA + e][rA] = pa[e];
            *reinterpret_cast<float4*>(&Bs[nb][kk][nn])     = pb0;
            *reinterpret_cast<float4*>(&Bs[nb][kk][nn + 4]) = pb1;
        }
        __syncthreads();
        buf ^= 1;
    }

    // ---- epilogue ----
    const int nc = n0 + tx * 4;
    if (MODE == 2) {
        float4 bv = *reinterpret_cast<const float4*>(bias + nc);
#pragma unroll
        for (int i = 0; i < 8; i++) {
            int r = ty * 8 + i;
            float4 o;
            o.x = acc[i][0] + bv.x;
            o.y = acc[i][1] + bv.y;
            o.z = acc[i][2] + bv.z;
            o.w = acc[i][3] + bv.w;
            *reinterpret_cast<float4*>(&g_logits[0][0] + (size_t)r * VV + nc) = o;
        }
    } else {
        float* P = &g_part[blockIdx.y][0][0];
#pragma unroll
        for (int i = 0; i < 8; i++) {
            int r = ty * 8 + i;
            float4 o;
            o.x = acc[i][0]; o.y = acc[i][1]; o.z = acc[i][2]; o.w = acc[i][3];
            *reinterpret_cast<float4*>(P + (size_t)r * 4096 + nc) = o;
        }
    }
}

// ---------------- LSTM cell: fused split-K reduce + bias + cell --------------
__device__ __forceinline__ float sigf(float x) { return 1.f / (1.f + expf(-x)); }

__global__ void cell_kernel(int layer, const float* __restrict__ bias) {
    int idx = blockIdx.x * blockDim.x + threadIdx.x;
    if (idx >= RR * HH) return;
    int r = idx >> 10, j = idx & (HH - 1);
    float* hA = layer ? &g_h1[0][0] : &g_h0[0][0];
    float* cA = layer ? &g_c1[0][0] : &g_c0[0][0];
    float gi = bias[j];
    float gf = bias[j + HH];
    float gg = bias[j + 2 * HH];
    float go = bias[j + 3 * HH];
#pragma unroll
    for (int s = 0; s < 4; s++) {
        gi += g_part[s][r][j];
        gf += g_part[s][r][j + HH];
        gg += g_part[s][r][j + 2 * HH];
        go += g_part[s][r][j + 3 * HH];
    }
    float c = cA[idx];
    c = sigf(gf) * c + sigf(gi) * tanhf(gg);
    float h = sigf(go) * tanhf(c);
    cA[idx] = c;
    hA[idx] = h;
}

// ---------------- softmax + p output + gumbel argmax sampling ----------------
__global__ __launch_bounds__(256) void sample_kernel(
    int t,
    uint32_t k0s0, uint32_t k1s0, uint32_t k0s1, uint32_t k1s1,
    const int* __restrict__ x, float* __restrict__ out)
{
    const int r   = blockIdx.x;
    const int tid = threadIdx.x;
    const int stream = (r < BB) ? 0 : 1;
    const int b   = r & 31;
    const float* L = g_logits[r];

    __shared__ float red[256];
    __shared__ int   redi[256];

    // pass 1: max
    float m = -INFINITY;
    for (int v = tid; v < VV; v += 256) m = fmaxf(m, L[v]);
    red[tid] = m; __syncthreads();
    for (int s = 128; s > 0; s >>= 1) {
        if (tid < s) red[tid] = fmaxf(red[tid], red[tid + s]);
        __syncthreads();
    }
    m = red[0]; __syncthreads();

    // pass 2: log-sum-exp
    float sum = 0.f;
    for (int v = tid; v < VV; v += 256) sum += expf(L[v] - m);
    red[tid] = sum; __syncthreads();
    for (int s = 128; s > 0; s >>= 1) {
        if (tid < s) red[tid] += red[tid + s];
        __syncthreads();
    }
    float lse = logf(red[0]); __syncthreads();

    // pass 3: write p, gumbel score, local argmax (first-index on ties)
    const uint32_t k0 = stream ? k0s1 : k0s0;
    const uint32_t k1 = stream ? k1s1 : k1s0;
    const size_t p_off = stream ? ((size_t)4096 + (size_t)BB * TT * VV + 4096)
                                : (size_t)4096;
    const size_t pbase = p_off + ((size_t)b * TT + t) * VV;

    float best = -INFINITY; int bidx = VV;
    for (int v = tid; v < VV; v += 256) {
        float lp = (L[v] - m) - lse;
        out[pbase + v] = expf(lp);
        float g = jax_gumbel(k0, k1, (uint32_t)(b * VV + v));
        float sc = lp + g;
        if (sc > best) { best = sc; bidx = v; }
    }
    red[tid] = best; redi[tid] = bidx; __syncthreads();
    for (int s = 128; s > 0; s >>= 1) {
        if (tid < s) {
            float o = red[tid + s]; int oi = redi[tid + s];
            if (o > red[tid] || (o == red[tid] && oi < redi[tid])) {
                red[tid] = o; redi[tid] = oi;
            }
        }
        __syncthreads();
    }

    if (tid == 0) {
        int am = redi[0];
        size_t sbase = stream ? ((size_t)4096 + (size_t)BB * TT * VV) : (size_t)0;
        out[sbase + (size_t)b * TT + t] = (float)am;
        g_tok[r] = stream ? x[(size_t)b * TT + t] : am;
    }
}

// ---------------- host driver ----------------
extern "C" void kernel_launch(void* const* d_in, const int* in_sizes, int n_in,
                              void* d_out, int out_size)
{
    const int*   x    = (const int*)  d_in[0];
    const float* z    = (const float*)d_in[1];
    const float* emb  = (const float*)d_in[2];
    const float* Wx0  = (const float*)d_in[3];
    const float* Wh0  = (const float*)d_in[4];
    const float* b0   = (const float*)d_in[5];
    const float* Wx1  = (const float*)d_in[6];
    const float* Wh1  = (const float*)d_in[7];
    const float* b1   = (const float*)d_in[8];
    const float* Wout = (const float*)d_in[9];
    const float* bout = (const float*)d_in[10];
    float* out = (float*)d_out;

    init_kernel<<<256, 256>>>();

    uint32_t s0a, s0b, s1a, s1b;
    h_fold(0u, 42u, 0u, &s0a, &s0b);
    h_fold(0u, 42u, 1u, &s1a, &s1b);

    for (int t = 0; t < TT; t++) {
        uint32_t k0s0, k1s0, k0s1, k1s1;
        h_fold(s0a, s0b, (uint32_t)t, &k0s0, &k1s0);
        h_fold(s1a, s1b, (uint32_t)t, &k0s1, &k1s1);

        gemm_kernel<0><<<dim3(32, 4), 256>>>(emb, z, Wx0, Wh0, b0);
        cell_kernel<<<(RR * HH + 255) / 256, 256>>>(0, b0);
        gemm_kernel<1><<<dim3(32, 4), 256>>>(emb, z, Wx1, Wh1, b1);
        cell_kernel<<<(RR * HH + 255) / 256, 256>>>(1, b1);
        gemm_kernel<2><<<dim3(125, 1), 256>>>(emb, z, Wout, Wout, bout);
        sample_kernel<<<RR, 256>>>(t, k0s0, k1s0, k0s1, k1s1, x, out);
    }
}

// round 6
// speedup vs baseline: 3.5127x; 1.2630x over previous
#include <cuda_runtime.h>
#include <cstdint>
#include <math.h>

#define BB 32
#define TT 128
#define VV 16000
#define EE 512
#define ZZ 128
#define HH 1024
#define RR 64   // 2*B rows: [0,32)=free-running (stream 0), [32,64)=teacher (stream 1)
#define START_ID 1
#define NSPLIT 8      // split-K for gate GEMMs

// ---------------- device state ----------------
__device__ float g_h0[RR][HH];
__device__ float g_c0[RR][HH];
__device__ float g_h1[RR][HH];
__device__ float g_c1[RR][HH];
__device__ float g_part[NSPLIT][RR][4*HH];   // split-K partials for gate GEMMs
__device__ float g_logits[RR][VV];
__device__ float g_lpart[RR][VV];            // split-K partial for logits GEMM
__device__ int   g_tok[RR];

// ---------------- init ----------------
__global__ void init_kernel() {
    int i = blockIdx.x * blockDim.x + threadIdx.x;
    if (i < RR * HH) {
        ((float*)g_h0)[i] = 0.f;
        ((float*)g_c0)[i] = 0.f;
        ((float*)g_h1)[i] = 0.f;
        ((float*)g_c1)[i] = 0.f;
    }
    if (i < RR) g_tok[i] = START_ID;
}

// ---------------- threefry2x32 (exact JAX semantics) ----------------
__host__ __device__ __forceinline__ uint32_t rotl32(uint32_t v, int d) {
    return (v << d) | (v >> (32 - d));
}

__host__ __device__ __forceinline__ void threefry2x32(
    uint32_t k0, uint32_t k1, uint32_t x0, uint32_t x1,
    uint32_t* o0, uint32_t* o1)
{
    uint32_t ks2 = k0 ^ k1 ^ 0x1BD11BDAu;
    x0 += k0; x1 += k1;
#define TF_RND(R_) { x0 += x1; x1 = rotl32(x1, R_); x1 ^= x0; }
    TF_RND(13) TF_RND(15) TF_RND(26) TF_RND(6)
    x0 += k1;  x1 += ks2 + 1u;
    TF_RND(17) TF_RND(29) TF_RND(16) TF_RND(24)
    x0 += ks2; x1 += k0 + 2u;
    TF_RND(13) TF_RND(15) TF_RND(26) TF_RND(6)
    x0 += k0;  x1 += k1 + 3u;
    TF_RND(17) TF_RND(29) TF_RND(16) TF_RND(24)
    x0 += k1;  x1 += ks2 + 4u;
    TF_RND(13) TF_RND(15) TF_RND(26) TF_RND(6)
    x0 += ks2; x1 += k0 + 5u;
#undef TF_RND
    *o0 = x0; *o1 = x1;
}

static void h_fold(uint32_t k0, uint32_t k1, uint32_t data, uint32_t* o0, uint32_t* o1) {
    threefry2x32(k0, k1, 0u, data, o0, o1);
}

// JAX >= 0.4.30 partitionable threefry: counter = u64(idx) -> (0, idx), bits = o0^o1
__device__ __forceinline__ float jax_gumbel(uint32_t k0, uint32_t k1, uint32_t idx) {
    uint32_t o0, o1;
    threefry2x32(k0, k1, 0u, idx, &o0, &o1);
    uint32_t bits = o0 ^ o1;
    float f = __uint_as_float((bits >> 9) | 0x3f800000u) - 1.0f;  // [0,1)
    float u = fmaxf(f, 1.17549435e-38f);                          // minval = tiny
    return -logf(-logf(u));
}

// ---------------- GEMM: M=64, BN=128, Kc=16, 256 thr, 8x4/thread, dbuf smem ----
// MODE 0: gates layer0, K=1664 (8 slices of 208), A=[emb[tok]|z|h0], B=[Wx0;Wh0]
// MODE 1: gates layer1, K=2048 (8 slices of 256), A=[h0|h1],         B=[Wx1;Wh1]
// MODE 2: logits,       K=1024 (2 slices of 512), A=h1,              B=Wout (+bias)
template<int MODE>
__device__ __forceinline__ void load_tile(
    int k0, int rA, int kkA, int n0, int tid,
    const float* __restrict__ emb, const float* __restrict__ z,
    const float* __restrict__ W1,  const float* __restrict__ W2,
    const int* toks, float pa[4], float4& pb0, float4& pb1)
{
#pragma unroll
    for (int e = 0; e < 4; e++) {
        int k = k0 + kkA + e;
        float v;
        if (MODE == 0) {
            if (k < 512)      v = emb[(size_t)toks[rA] * EE + k];
            else if (k < 640) v = z[(size_t)(rA & 31) * ZZ + (k - 512)];
            else              v = g_h0[rA][k - 640];
        } else if (MODE == 1) {
            v = (k < 1024) ? g_h0[rA][k] : g_h1[rA][k - 1024];
        } else {
            v = g_h1[rA][k];
        }
        pa[e] = v;
    }
    {
        int kk = tid >> 4;
        int nn = (tid & 15) * 8;
        int k  = k0 + kk;
        const float* row;
        if (MODE == 0)      row = (k < 640)  ? (W1 + (size_t)k * 4096)
                                             : (W2 + (size_t)(k - 640) * 4096);
        else if (MODE == 1) row = (k < 1024) ? (W1 + (size_t)k * 4096)
                                             : (W2 + (size_t)(k - 1024) * 4096);
        else                row = W1 + (size_t)k * VV;
        pb0 = *reinterpret_cast<const float4*>(row + n0 + nn);
        pb1 = *reinterpret_cast<const float4*>(row + n0 + nn + 4);
    }
}

template<int MODE>
__global__ __launch_bounds__(256) void gemm_kernel(
    const float* __restrict__ emb, const float* __restrict__ z,
    const float* __restrict__ W1,  const float* __restrict__ W2,
    const float* __restrict__ bias)
{
    constexpr int KTOT = (MODE == 0) ? 1664 : ((MODE == 1) ? 2048 : 1024);
    constexpr int KSL  = (MODE == 2) ? 2 : NSPLIT;
    constexpr int KS   = KTOT / KSL;     // 208 / 256 / 512

    __shared__ float As[2][16][64];
    __shared__ float Bs[2][16][128];
    __shared__ int   toks[64];

    const int tid = threadIdx.x;
    const int n0  = blockIdx.x * 128;
    const int ks0 = blockIdx.y * KS;
    const int tx  = tid & 31;
    const int ty  = tid >> 5;
    const int rA  = tid >> 2;
    const int kkA = (tid & 3) * 4;

    if (MODE == 0) {
        if (tid < 64) toks[tid] = g_tok[tid];
        __syncthreads();
    }

    float acc[8][4];
#pragma unroll
    for (int i = 0; i < 8; i++)
#pragma unroll
        for (int j = 0; j < 4; j++) acc[i][j] = 0.f;

    float pa[4]; float4 pb0, pb1;

    // preload slice 0 -> buffer 0
    load_tile<MODE>(ks0, rA, kkA, n0, tid, emb, z, W1, W2, toks, pa, pb0, pb1);
    {
        int kk = tid >> 4, nn = (tid & 15) * 8;
#pragma unroll
        for (int e = 0; e < 4; e++) As[0][kkA + e][rA] = pa[e];
        *reinterpret_cast<float4*>(&Bs[0][kk][nn])     = pb0;
        *reinterpret_cast<float4*>(&Bs[0][kk][nn + 4]) = pb1;
    }
    __syncthreads();

    int buf = 0;
    for (int k0 = ks0; k0 < ks0 + KS; k0 += 16) {
        const bool more = (k0 + 16) < (ks0 + KS);
        if (more)
            load_tile<MODE>(k0 + 16, rA, kkA, n0, tid, emb, z, W1, W2, toks, pa, pb0, pb1);

        // compute current buffer
#pragma unroll
        for (int kk = 0; kk < 16; kk++) {
            float4 a0 = *reinterpret_cast<const float4*>(&As[buf][kk][ty * 8]);
            float4 a1 = *reinterpret_cast<const float4*>(&As[buf][kk][ty * 8 + 4]);
            float4 b4 = *reinterpret_cast<const float4*>(&Bs[buf][kk][tx * 4]);
            float a[8] = {a0.x, a0.y, a0.z, a0.w, a1.x, a1.y, a1.z, a1.w};
#pragma unroll
            for (int i = 0; i < 8; i++) {
                acc[i][0] += a[i] * b4.x;
                acc[i][1] += a[i] * b4.y;
                acc[i][2] += a[i] * b4.z;
                acc[i][3] += a[i] * b4.w;
            }
        }

        if (more) {
            int kk = tid >> 4, nn = (tid & 15) * 8;
            int nb = buf ^ 1;
#pragma unroll
            for (int e = 0; e < 4; e++) As[nb][kkA + e][rA] = pa[e];
            *reinterpret_cast<float4*>(&Bs[nb][kk][nn])     = pb0;
            *reinterpret_cast<float4*>(&Bs[nb][kk][nn + 4]) = pb1;
        }
        __syncthreads();
        buf ^= 1;
    }

    // ---- epilogue ----
    const int nc = n0 + tx * 4;
    if (MODE == 2) {
        if (blockIdx.y == 0) {
            float4 bv = *reinterpret_cast<const float4*>(bias + nc);
#pragma unroll
            for (int i = 0; i < 8; i++) {
                int r = ty * 8 + i;
                float4 o;
                o.x = acc[i][0] + bv.x;
                o.y = acc[i][1] + bv.y;
                o.z = acc[i][2] + bv.z;
                o.w = acc[i][3] + bv.w;
                *reinterpret_cast<float4*>(&g_logits[0][0] + (size_t)r * VV + nc) = o;
            }
        } else {
#pragma unroll
            for (int i = 0; i < 8; i++) {
                int r = ty * 8 + i;
                float4 o;
                o.x = acc[i][0]; o.y = acc[i][1]; o.z = acc[i][2]; o.w = acc[i][3];
                *reinterpret_cast<float4*>(&g_lpart[0][0] + (size_t)r * VV + nc) = o;
            }
        }
    } else {
        float* P = &g_part[blockIdx.y][0][0];
#pragma unroll
        for (int i = 0; i < 8; i++) {
            int r = ty * 8 + i;
            float4 o;
            o.x = acc[i][0]; o.y = acc[i][1]; o.z = acc[i][2]; o.w = acc[i][3];
            *reinterpret_cast<float4*>(P + (size_t)r * 4096 + nc) = o;
        }
    }
}

// ---------------- LSTM cell: fused split-K reduce + bias + cell --------------
__device__ __forceinline__ float sigf(float x) { return 1.f / (1.f + expf(-x)); }

__global__ void cell_kernel(int layer, const float* __restrict__ bias) {
    int idx4 = blockIdx.x * blockDim.x + threadIdx.x;   // over RR*HH/4
    if (idx4 >= RR * HH / 4) return;
    int r = idx4 >> 8;            // HH/4 = 256
    int j = (idx4 & 255) * 4;
    float* hA = layer ? &g_h1[0][0] : &g_h0[0][0];
    float* cA = layer ? &g_c1[0][0] : &g_c0[0][0];

    float4 gi = *reinterpret_cast<const float4*>(bias + j);
    float4 gf = *reinterpret_cast<const float4*>(bias + j + HH);
    float4 gg = *reinterpret_cast<const float4*>(bias + j + 2 * HH);
    float4 go = *reinterpret_cast<const float4*>(bias + j + 3 * HH);
#pragma unroll
    for (int s = 0; s < NSPLIT; s++) {
        float4 a = *reinterpret_cast<const float4*>(&g_part[s][r][j]);
        float4 b = *reinterpret_cast<const float4*>(&g_part[s][r][j + HH]);
        float4 c = *reinterpret_cast<const float4*>(&g_part[s][r][j + 2 * HH]);
        float4 d = *reinterpret_cast<const float4*>(&g_part[s][r][j + 3 * HH]);
        gi.x += a.x; gi.y += a.y; gi.z += a.z; gi.w += a.w;
        gf.x += b.x; gf.y += b.y; gf.z += b.z; gf.w += b.w;
        gg.x += c.x; gg.y += c.y; gg.z += c.z; gg.w += c.w;
        go.x += d.x; go.y += d.y; go.z += d.z; go.w += d.w;
    }
    float4 cc = *reinterpret_cast<const float4*>(cA + (size_t)r * HH + j);
    float4 hh;
    cc.x = sigf(gf.x) * cc.x + sigf(gi.x) * tanhf(gg.x);
    cc.y = sigf(gf.y) * cc.y + sigf(gi.y) * tanhf(gg.y);
    cc.z = sigf(gf.z) * cc.z + sigf(gi.z) * tanhf(gg.z);
    cc.w = sigf(gf.w) * cc.w + sigf(gi.w) * tanhf(gg.w);
    hh.x = sigf(go.x) * tanhf(cc.x);
    hh.y = sigf(go.y) * tanhf(cc.y);
    hh.z = sigf(go.z) * tanhf(cc.z);
    hh.w = sigf(go.w) * tanhf(cc.w);
    *reinterpret_cast<float4*>(cA + (size_t)r * HH + j) = cc;
    *reinterpret_cast<float4*>(hA + (size_t)r * HH + j) = hh;
}

// ---------------- softmax + p output + gumbel argmax sampling ----------------
// Fuses the logits split-K reduction: L = g_logits(+bias already) + g_lpart.
#define STH 512
__global__ __launch_bounds__(STH) void sample_kernel(
    int t,
    uint32_t k0s0, uint32_t k1s0, uint32_t k0s1, uint32_t k1s1,
    const int* __restrict__ x, float* __restrict__ out)
{
    const int r   = blockIdx.x;
    const int tid = threadIdx.x;
    const int stream = (r < BB) ? 0 : 1;
    const int b   = r & 31;
    float4* L4  = reinterpret_cast<float4*>(&g_logits[r][0]);
    const float4* P4 = reinterpret_cast<const float4*>(&g_lpart[r][0]);
    constexpr int NV4 = VV / 4;   // 4000

    __shared__ float red[STH];
    __shared__ int   redi[STH];

    // pass 1: reduce split-K, store back, max
    float m = -INFINITY;
    for (int v4 = tid; v4 < NV4; v4 += STH) {
        float4 a = L4[v4];
        float4 p = P4[v4];
        a.x += p.x; a.y += p.y; a.z += p.z; a.w += p.w;
        L4[v4] = a;
        m = fmaxf(m, fmaxf(fmaxf(a.x, a.y), fmaxf(a.z, a.w)));
    }
    red[tid] = m; __syncthreads();
    for (int s = STH / 2; s > 0; s >>= 1) {
        if (tid < s) red[tid] = fmaxf(red[tid], red[tid + s]);
        __syncthreads();
    }
    m = red[0]; __syncthreads();

    // pass 2: log-sum-exp
    float sum = 0.f;
    for (int v4 = tid; v4 < NV4; v4 += STH) {
        float4 a = L4[v4];
        sum += expf(a.x - m) + expf(a.y - m) + expf(a.z - m) + expf(a.w - m);
    }
    red[tid] = sum; __syncthreads();
    for (int s = STH / 2; s > 0; s >>= 1) {
        if (tid < s) red[tid] += red[tid + s];
        __syncthreads();
    }
    float lse = logf(red[0]); __syncthreads();

    // pass 3: write p, gumbel score, local argmax (first-index on ties)
    const uint32_t k0 = stream ? k0s1 : k0s0;
    const uint32_t k1 = stream ? k1s1 : k1s0;
    const size_t p_off = stream ? ((size_t)4096 + (size_t)BB * TT * VV + 4096)
                                : (size_t)4096;
    const size_t pbase = p_off + ((size_t)b * TT + t) * VV;
    float4* O4 = reinterpret_cast<float4*>(out + pbase);

    float best = -INFINITY; int bidx = VV;
    for (int v4 = tid; v4 < NV4; v4 += STH) {
        float4 a = L4[v4];
        float lp[4] = {a.x - m - lse, a.y - m - lse, a.z - m - lse, a.w - m - lse};
        float4 pw;
        pw.x = expf(lp[0]); pw.y = expf(lp[1]); pw.z = expf(lp[2]); pw.w = expf(lp[3]);
        O4[v4] = pw;
#pragma unroll
        for (int e = 0; e < 4; e++) {
            int v = v4 * 4 + e;
            float g = jax_gumbel(k0, k1, (uint32_t)(b * VV + v));
            float sc = lp[e] + g;
            if (sc > best) { best = sc; bidx = v; }
        }
    }
    red[tid] = best; redi[tid] = bidx; __syncthreads();
    for (int s = STH / 2; s > 0; s >>= 1) {
        if (tid < s) {
            float o = red[tid + s]; int oi = redi[tid + s];
            if (o > red[tid] || (o == red[tid] && oi < redi[tid])) {
                red[tid] = o; redi[tid] = oi;
            }
        }
        __syncthreads();
    }

    if (tid == 0) {
        int am = redi[0];
        size_t sbase = stream ? ((size_t)4096 + (size_t)BB * TT * VV) : (size_t)0;
        out[sbase + (size_t)b * TT + t] = (float)am;
        g_tok[r] = stream ? x[(size_t)b * TT + t] : am;
    }
}

// ---------------- host driver ----------------
extern "C" void kernel_launch(void* const* d_in, const int* in_sizes, int n_in,
                              void* d_out, int out_size)
{
    const int*   x    = (const int*)  d_in[0];
    const float* z    = (const float*)d_in[1];
    const float* emb  = (const float*)d_in[2];
    const float* Wx0  = (const float*)d_in[3];
    const float* Wh0  = (const float*)d_in[4];
    const float* b0   = (const float*)d_in[5];
    const float* Wx1  = (const float*)d_in[6];
    const float* Wh1  = (const float*)d_in[7];
    const float* b1   = (const float*)d_in[8];
    const float* Wout = (const float*)d_in[9];
    const float* bout = (const float*)d_in[10];
    float* out = (float*)d_out;

    init_kernel<<<256, 256>>>();

    uint32_t s0a, s0b, s1a, s1b;
    h_fold(0u, 42u, 0u, &s0a, &s0b);
    h_fold(0u, 42u, 1u, &s1a, &s1b);

    for (int t = 0; t < TT; t++) {
        uint32_t k0s0, k1s0, k0s1, k1s1;
        h_fold(s0a, s0b, (uint32_t)t, &k0s0, &k1s0);
        h_fold(s1a, s1b, (uint32_t)t, &k0s1, &k1s1);

        gemm_kernel<0><<<dim3(32, NSPLIT), 256>>>(emb, z, Wx0, Wh0, b0);
        cell_kernel<<<(RR * HH / 4 + 255) / 256, 256>>>(0, b0);
        gemm_kernel<1><<<dim3(32, NSPLIT), 256>>>(emb, z, Wx1, Wh1, b1);
        cell_kernel<<<(RR * HH / 4 + 255) / 256, 256>>>(1, b1);
        gemm_kernel<2><<<dim3(125, 2), 256>>>(emb, z, Wout, Wout, bout);
        sample_kernel<<<RR, STH>>>(t, k0s0, k1s0, k0s1, k1s1, x, out);
    }
}